// round 3
// baseline (speedup 1.0000x reference)
#include <cuda_runtime.h>

#define NC 128
#define EPS 1e-5f
#define RAYS_PER_CTA 8          // 8 warps/CTA, one ray per warp
#define THREADS (RAYS_PER_CTA * 32)

__device__ __forceinline__ float warp_incl_scan(float v, int lane) {
    #pragma unroll
    for (int o = 1; o < 32; o <<= 1) {
        float n = __shfl_up_sync(0xffffffffu, v, o);
        if (lane >= o) v += n;
    }
    return v;
}

__global__ __launch_bounds__(THREADS) void pdf_sampler_kernel(
    const float* __restrict__ deltas,
    const float* __restrict__ density,
    const float* __restrict__ bins,
    const float* __restrict__ u,
    float* __restrict__ out)
{
    const int lane = threadIdx.x & 31;
    const int wrp  = threadIdx.x >> 5;
    const int ray  = blockIdx.x * RAYS_PER_CTA + wrp;

    __shared__ float cdfv_sh[RAYS_PER_CTA][NC];      // cdf[1..128]
    __shared__ float bins_sh[RAYS_PER_CTA][NC + 1];

    const size_t base_c = (size_t)ray * NC;
    const size_t base_b = (size_t)ray * (NC + 1);

    // ---- coalesced loads ----
    const float4 dv = *(const float4*)(deltas  + base_c + 4 * lane);
    const float4 rv = *(const float4*)(density + base_c + 4 * lane);
    const float4 uv = *(const float4*)(u       + base_c + 4 * lane);

    bins_sh[wrp][lane]      = bins[base_b + lane];
    bins_sh[wrp][lane + 32] = bins[base_b + lane + 32];
    bins_sh[wrp][lane + 64] = bins[base_b + lane + 64];
    bins_sh[wrp][lane + 96] = bins[base_b + lane + 96];
    if (lane == 0) bins_sh[wrp][NC] = bins[base_b + NC];

    // ---- dd = delta * density, per-lane serial inclusive prefix ----
    const float dd0 = dv.x * rv.x;
    const float dd1 = dv.y * rv.y;
    const float dd2 = dv.z * rv.z;
    const float dd3 = dv.w * rv.w;
    const float p0 = dd0;
    const float p1 = p0 + dd1;
    const float p2 = p1 + dd2;
    const float p3 = p2 + dd3;

    // single warp scan of lane totals -> exclusive lane offset
    const float incl = warp_incl_scan(p3, lane);
    const float off  = incl - p3;

    // Telescoped cumulative weights: cumsum(w)[e] = 1 - exp(-cumsum(dd)[e])
    const float cw0 = 1.0f - __expf(-(off + p0));
    const float cw1 = 1.0f - __expf(-(off + p1));
    const float cw2 = 1.0f - __expf(-(off + p2));
    const float cw3 = 1.0f - __expf(-(off + p3));

    const float total = __shfl_sync(0xffffffffu, incl, 31);
    const float wsum  = 1.0f - __expf(-total);
    const float pad   = fmaxf(EPS - wsum, 0.0f);
    const float inv   = 1.0f / (wsum + pad);
    const float ps    = pad * (1.0f / (float)NC);

    const int e = 4 * lane;
    float4 cv;
    cv.x = fminf(1.0f, (cw0 + ps * (float)(e + 1)) * inv);
    cv.y = fminf(1.0f, (cw1 + ps * (float)(e + 2)) * inv);
    cv.z = fminf(1.0f, (cw2 + ps * (float)(e + 3)) * inv);
    cv.w = fminf(1.0f, (cw3 + ps * (float)(e + 4)) * inv);
    *(float4*)(&cdfv_sh[wrp][4 * lane]) = cv;   // aligned, conflict-free

    __syncwarp();

    // ---- per-sample inverse CDF ----
    // cd[i] = cdf[i+1]; count = #{cd[k] <= u}; below = count, above = min(count+1,128)
    const float* __restrict__ cd = cdfv_sh[wrp];
    const float* __restrict__ bn = bins_sh[wrp];
    float4 res;

    #pragma unroll
    for (int i = 0; i < 4; i++) {
        const float uu = (i == 0) ? uv.x : (i == 1) ? uv.y : (i == 2) ? uv.z : uv.w;

        // 5 scalar levels -> pos aligned to 4; track last successful probe value
        int pos = 0;
        float c0cand = 0.0f;                 // cdf[pos] when pos==0 handled: cdf[0]=0
        #pragma unroll
        for (int step = 64; step >= 4; step >>= 1) {
            const float tv = cd[pos + step - 1];
            if (tv <= uu) { pos += step; c0cand = tv; }
        }
        // vector tail: resolves final 2 levels + supplies c0/c1 from registers
        const float4 v = *(const float4*)(cd + pos);   // 16B aligned
        const int k = (v.x <= uu) + (v.y <= uu) + (v.z <= uu);
        const int fin = pos + k;                       // fin in [0,127]

        const float c1 = (k == 0) ? v.x : (k == 1) ? v.y : (k == 2) ? v.z : v.w;
        const float c0 = (k == 0) ? c0cand : (k == 1) ? v.x : (k == 2) ? v.y : v.z;

        const float b0 = bn[fin];
        const float b1 = bn[fin + 1];

        float den = c1 - c0;
        den = (den < EPS) ? 1.0f : den;
        const float frac = (uu - c0) / den;
        const float s = b0 + frac * (b1 - b0);
        if (i == 0) res.x = s; else if (i == 1) res.y = s; else if (i == 2) res.z = s; else res.w = s;
    }

    *(float4*)(out + base_c + 4 * lane) = res;
}

extern "C" void kernel_launch(void* const* d_in, const int* in_sizes, int n_in,
                              void* d_out, int out_size) {
    const float* deltas  = (const float*)d_in[0];
    const float* density = (const float*)d_in[1];
    const float* bins    = (const float*)d_in[2];
    const float* u       = (const float*)d_in[3];
    float* out = (float*)d_out;

    int R = in_sizes[0] / NC;               // 131072
    pdf_sampler_kernel<<<R / RAYS_PER_CTA, THREADS>>>(deltas, density, bins, u, out);
}